// round 14
// baseline (speedup 1.0000x reference)
#include <cuda_runtime.h>
#include <cuda_bf16.h>

// Problem constants (fixed by the reference)
#define CSEG 4096
#define ED   16
#define PIX  (1024*1024)
#define NEDGE 16384
#define DELTA_VAR  0.5f
#define DELTA_DIST 1.5f

#define GRID_F 148
#define TBLK   1024
#define STRIDE (GRID_F * TBLK)
#define MAXP   7                       // ceil(PIX / STRIDE)

// dynamic smem: 4096 rows x 8 uint32 (bf16x2 means) + 4096 f32 invn
#define SMEM_MEAN_BYTES (CSEG * 8 * 4)                 // 131072
#define SMEM_DYN        (SMEM_MEAN_BYTES + CSEG * 4)   // 147456

// All replay-mutable scratch in ONE struct so a single memset node zeroes it.
struct SState {
    float sums[CSEG * ED];     // segment sums (atomic target)
    float counts[CSEG];
    float acc[2];              // [0]=inter, [1]=intra
    unsigned int bar;          // phase barrier counter
    unsigned int done;         // finalize counter
};
__device__ __align__(128) SState g_state;

// ---------------------------------------------------------------------------
__device__ __forceinline__ void red_add_v4(float* addr, float a, float b, float c, float d) {
    asm volatile("red.global.add.v4.f32 [%0], {%1, %2, %3, %4};"
                 :: "l"(addr), "f"(a), "f"(b), "f"(c), "f"(d) : "memory");
}

__device__ __forceinline__ float warp_reduce(float v) {
    v += __shfl_down_sync(0xFFFFFFFFu, v, 16);
    v += __shfl_down_sync(0xFFFFFFFFu, v, 8);
    v += __shfl_down_sync(0xFFFFFFFFu, v, 4);
    v += __shfl_down_sync(0xFFFFFFFFu, v, 2);
    v += __shfl_down_sync(0xFFFFFFFFu, v, 1);
    return v;
}

__device__ __forceinline__ float block_reduce(float v, float* s) {
    int lane = threadIdx.x & 31;
    int wid  = threadIdx.x >> 5;
    v = warp_reduce(v);
    if (lane == 0) s[wid] = v;
    __syncthreads();
    if (wid == 0) {
        v = (lane < (TBLK >> 5)) ? s[lane] : 0.0f;
        v = warp_reduce(v);
    }
    return v;
}

// ---------------------------------------------------------------------------
// k_all: phase 1 = segment sums via L2 vector reductions; spin-barrier;
// phase 2 = bf16 mean table in smem, intra hinge (labels cached in regs),
// inter hinge over edges, block reductions, last-block finalize.
__global__ void __launch_bounds__(TBLK, 1) k_all(const float* __restrict__ emb,
                                                 const int*   __restrict__ seg,
                                                 const int*   __restrict__ edges,
                                                 const float* __restrict__ w,
                                                 float* __restrict__ out) {
    extern __shared__ char dyn[];
    unsigned int* s_mean = (unsigned int*)dyn;               // [CSEG*8] bf16x2
    float*        s_invn = (float*)(dyn + SMEM_MEAN_BYTES);  // [CSEG]
    __shared__ float sred[32];

    const int gid = blockIdx.x * TBLK + threadIdx.x;

    // ---- phase 1: segment sums + counts (labels cached for phase 2) ----
    int lab[MAXP];
    int np = 0;
#pragma unroll
    for (int it = 0; it < MAXP; it++) {
        int p = gid + it * STRIDE;
        if (p < PIX) {
            int c = seg[p];
            lab[it] = c;
            np = it + 1;
            float v[ED];
#pragma unroll
            for (int e = 0; e < ED; e++) v[e] = emb[(size_t)e * PIX + p];
            float* base = &g_state.sums[c * ED];
            red_add_v4(base +  0, v[0],  v[1],  v[2],  v[3]);
            red_add_v4(base +  4, v[4],  v[5],  v[6],  v[7]);
            red_add_v4(base +  8, v[8],  v[9],  v[10], v[11]);
            red_add_v4(base + 12, v[12], v[13], v[14], v[15]);
            atomicAdd(&g_state.counts[c], 1.0f);
        }
    }

    // ---- grid-wide barrier (grid == 1 wave, spin is safe) ----
    __threadfence();               // flush REDs before signaling
    __syncthreads();
    if (threadIdx.x == 0) {
        atomicAdd(&g_state.bar, 1u);
        while (atomicAdd(&g_state.bar, 0u) < GRID_F) { }
    }
    __syncthreads();
    __threadfence();               // acquire side

    // ---- build smem table: bf16x2 means + fp32 invn ----
    for (int s = threadIdx.x; s < CSEG; s += TBLK) {
        const float4* src = (const float4*)&g_state.sums[s * ED];
        float4 a = __ldcg(src + 0), b = __ldcg(src + 1);
        float4 c4 = __ldcg(src + 2), d = __ldcg(src + 3);
        float inv = __frcp_rn(fmaxf(__ldcg(&g_state.counts[s]), 1.0f));
        float m[ED] = { a.x*inv,  a.y*inv,  a.z*inv,  a.w*inv,
                        b.x*inv,  b.y*inv,  b.z*inv,  b.w*inv,
                        c4.x*inv, c4.y*inv, c4.z*inv, c4.w*inv,
                        d.x*inv,  d.y*inv,  d.z*inv,  d.w*inv };
        unsigned int* row = &s_mean[s * 8];
#pragma unroll
        for (int j = 0; j < 8; j++) {
            __nv_bfloat162 h = __floats2bfloat162_rn(m[2*j], m[2*j + 1]);
            row[j] = *(unsigned int*)&h;
        }
        s_invn[s] = inv;
    }
    __syncthreads();

    // ---- phase 2a: intra hinge (emb re-read is L2-warm; labels from regs) ----
    float h_intra = 0.0f;
#pragma unroll
    for (int it = 0; it < MAXP; it++) {
        if (it < np) {
            int p = gid + it * STRIDE;
            int c = lab[it];
            float v[ED];
#pragma unroll
            for (int e = 0; e < ED; e++) v[e] = emb[(size_t)e * PIX + p];
            const uint4* row = (const uint4*)&s_mean[c * 8];
            uint4 r0 = row[0], r1 = row[1];
            unsigned int u[8] = { r0.x, r0.y, r0.z, r0.w, r1.x, r1.y, r1.z, r1.w };
            float dot = 0.0f;
#pragma unroll
            for (int j = 0; j < 8; j++) {
                float lo = __uint_as_float(u[j] << 16);
                float hi = __uint_as_float(u[j] & 0xFFFF0000u);
                dot += lo * v[2*j] + hi * v[2*j + 1];
            }
            h_intra += fmaxf(0.5f - dot, 0.0f) * s_invn[c];   // (1-dot)-0.5
        }
    }

    // ---- phase 2b: inter hinge (first 16 blocks cover all edges) ----
    float h_inter = 0.0f;
    if (gid < NEDGE) {
        int eu = edges[gid];
        int ev = edges[NEDGE + gid];
        const uint4* ru4 = (const uint4*)&s_mean[eu * 8];
        const uint4* rv4 = (const uint4*)&s_mean[ev * 8];
        uint4 a0 = ru4[0], a1 = ru4[1], b0 = rv4[0], b1 = rv4[1];
        unsigned int ua[8] = { a0.x, a0.y, a0.z, a0.w, a1.x, a1.y, a1.z, a1.w };
        unsigned int ub[8] = { b0.x, b0.y, b0.z, b0.w, b1.x, b1.y, b1.z, b1.w };
        float dm = 0.0f;
#pragma unroll
        for (int j = 0; j < 8; j++) {
            float alo = __uint_as_float(ua[j] << 16);
            float ahi = __uint_as_float(ua[j] & 0xFFFF0000u);
            float blo = __uint_as_float(ub[j] << 16);
            float bhi = __uint_as_float(ub[j] & 0xFFFF0000u);
            dm += alo * blo + ahi * bhi;
        }
        float d_inter = 1.0f - dm;
        h_inter = fmaxf(DELTA_DIST - d_inter * w[gid], 0.0f);
    }

    // ---- reductions + finalize ----
    float t1 = block_reduce(h_intra, sred);
    if (threadIdx.x == 0) atomicAdd(&g_state.acc[1], t1);
    __syncthreads();
    float t0 = block_reduce(h_inter, sred);
    if (threadIdx.x == 0) atomicAdd(&g_state.acc[0], t0);

    if (threadIdx.x == 0) {
        __threadfence();
        unsigned int v = atomicAdd(&g_state.done, 1u);
        if (v == GRID_F - 1) {
            float inter = atomicAdd(&g_state.acc[0], 0.0f);
            float intra = atomicAdd(&g_state.acc[1], 0.0f);
            out[0] = inter / (float)NEDGE + intra / (float)CSEG;
        }
    }
}

// ---------------------------------------------------------------------------
extern "C" void kernel_launch(void* const* d_in, const int* in_sizes, int n_in,
                              void* d_out, int out_size) {
    const float* emb   = (const float*)d_in[0];   // (1,16,1024,1024) f32
    const float* w     = (const float*)d_in[1];   // (NE,) f32
    const int*   seg   = (const int*)  d_in[2];   // (1,1,1024,1024) i32
    const int*   edges = (const int*)  d_in[3];   // (2,NE) i32
    float*       out   = (float*)d_out;

    static void* state_ptr = nullptr;             // resolved once; fixed address
    if (!state_ptr) cudaGetSymbolAddress(&state_ptr, g_state);

    cudaFuncSetAttribute(k_all, cudaFuncAttributeMaxDynamicSharedMemorySize, SMEM_DYN);

    // Single memset node zeroes sums/counts/acc/bar/done (all-zero bytes).
    cudaMemsetAsync(state_ptr, 0, sizeof(SState));
    k_all<<<GRID_F, TBLK, SMEM_DYN>>>(emb, seg, edges, w, out);
}

// round 15
// speedup vs baseline: 1.0654x; 1.0654x over previous
#include <cuda_runtime.h>
#include <cuda_bf16.h>

// Problem constants (fixed by the reference)
#define CSEG 4096
#define ED   16
#define PIX  (1024*1024)
#define NEDGE 16384
#define DELTA_VAR  0.5f
#define DELTA_DIST 1.5f

#define GRID_F 148
#define TBLK   1024
// dynamic smem: 4096 rows x 8 uint32 (bf16x2 means) + 4096 f32 invn
#define SMEM_MEAN_BYTES (CSEG * 8 * 4)                 // 131072
#define SMEM_DYN        (SMEM_MEAN_BYTES + CSEG * 4)   // 147456

// All replay-mutable scratch in ONE struct: a single memset node zeroes it.
struct SState {
    float sums[CSEG * ED];     // segment sums (atomic target)
    float counts[CSEG];
    float acc[2];              // [0]=inter, [1]=intra
    unsigned int done;         // finalize counter
};
__device__ __align__(128) SState g_state;

// ---------------------------------------------------------------------------
__device__ __forceinline__ void red_add_v4(float* addr, float a, float b, float c, float d) {
    asm volatile("red.global.add.v4.f32 [%0], {%1, %2, %3, %4};"
                 :: "l"(addr), "f"(a), "f"(b), "f"(c), "f"(d) : "memory");
}

__device__ __forceinline__ float warp_reduce(float v) {
    v += __shfl_down_sync(0xFFFFFFFFu, v, 16);
    v += __shfl_down_sync(0xFFFFFFFFu, v, 8);
    v += __shfl_down_sync(0xFFFFFFFFu, v, 4);
    v += __shfl_down_sync(0xFFFFFFFFu, v, 2);
    v += __shfl_down_sync(0xFFFFFFFFu, v, 1);
    return v;
}

__device__ __forceinline__ float block_reduce(float v, float* s) {
    int lane = threadIdx.x & 31;
    int wid  = threadIdx.x >> 5;
    v = warp_reduce(v);
    if (lane == 0) s[wid] = v;
    __syncthreads();
    if (wid == 0) {
        v = (lane < (TBLK >> 5)) ? s[lane] : 0.0f;
        v = warp_reduce(v);
    }
    return v;
}

// ---------------------------------------------------------------------------
// k_segsum: segment sums + counts. 256-thread blocks for high occupancy/MLP.
// Count-red issued first so it overlaps the 16 channel loads.
__global__ void __launch_bounds__(256) k_segsum(const float* __restrict__ emb,
                                                const int*   __restrict__ seg) {
    int p = blockIdx.x * blockDim.x + threadIdx.x;
    int c = seg[p];
    atomicAdd(&g_state.counts[c], 1.0f);
    float v[ED];
#pragma unroll
    for (int e = 0; e < ED; e++) v[e] = emb[(size_t)e * PIX + p];
    float* base = &g_state.sums[c * ED];
    red_add_v4(base +  0, v[0],  v[1],  v[2],  v[3]);
    red_add_v4(base +  4, v[4],  v[5],  v[6],  v[7]);
    red_add_v4(base +  8, v[8],  v[9],  v[10], v[11]);
    red_add_v4(base + 12, v[12], v[13], v[14], v[15]);
}

// k_fused: smem-resident bf16 mean table (144 KB), then intra hinge over all
// pixels (grid-stride), inter hinge over edges, last-block finalize.
__global__ void __launch_bounds__(TBLK, 1) k_fused(const float* __restrict__ emb,
                                                   const int*   __restrict__ seg,
                                                   const int*   __restrict__ edges,
                                                   const float* __restrict__ w,
                                                   float* __restrict__ out) {
    extern __shared__ char dyn[];
    unsigned int* s_mean = (unsigned int*)dyn;               // [CSEG*8] bf16x2
    float*        s_invn = (float*)(dyn + SMEM_MEAN_BYTES);  // [CSEG]
    __shared__ float sred[32];

    // ---- build the table: means (bf16x2 packed) + invn ----
    for (int s = threadIdx.x; s < CSEG; s += TBLK) {
        const float4* src = (const float4*)&g_state.sums[s * ED];
        float4 a = src[0], b = src[1], c4 = src[2], d = src[3];
        float inv = __frcp_rn(fmaxf(g_state.counts[s], 1.0f));
        float m[ED] = { a.x*inv,  a.y*inv,  a.z*inv,  a.w*inv,
                        b.x*inv,  b.y*inv,  b.z*inv,  b.w*inv,
                        c4.x*inv, c4.y*inv, c4.z*inv, c4.w*inv,
                        d.x*inv,  d.y*inv,  d.z*inv,  d.w*inv };
        unsigned int* row = &s_mean[s * 8];
#pragma unroll
        for (int j = 0; j < 8; j++) {
            __nv_bfloat162 h = __floats2bfloat162_rn(m[2*j], m[2*j + 1]);
            row[j] = *(unsigned int*)&h;
        }
        s_invn[s] = inv;
    }
    __syncthreads();

    // ---- intra term: grid-stride over pixels (emb is L2-warm) ----
    float h_intra = 0.0f;
    for (int p = blockIdx.x * TBLK + threadIdx.x; p < PIX; p += GRID_F * TBLK) {
        int c = seg[p];
        float v[ED];
#pragma unroll
        for (int e = 0; e < ED; e++) v[e] = emb[(size_t)e * PIX + p];
        const uint4* row = (const uint4*)&s_mean[c * 8];
        uint4 r0 = row[0], r1 = row[1];
        unsigned int u[8] = { r0.x, r0.y, r0.z, r0.w, r1.x, r1.y, r1.z, r1.w };
        float dot = 0.0f;
#pragma unroll
        for (int j = 0; j < 8; j++) {
            float lo = __uint_as_float(u[j] << 16);
            float hi = __uint_as_float(u[j] & 0xFFFF0000u);
            dot += lo * v[2*j] + hi * v[2*j + 1];
        }
        h_intra += fmaxf(0.5f - dot, 0.0f) * s_invn[c];   // (1-dot)-DELTA_VAR
    }

    // ---- inter term: first 16 blocks cover all 16384 edges ----
    float h_inter = 0.0f;
    int ei = blockIdx.x * TBLK + threadIdx.x;
    if (ei < NEDGE) {
        int eu = edges[ei];
        int ev = edges[NEDGE + ei];
        const uint4* ru4 = (const uint4*)&s_mean[eu * 8];
        const uint4* rv4 = (const uint4*)&s_mean[ev * 8];
        uint4 a0 = ru4[0], a1 = ru4[1], b0 = rv4[0], b1 = rv4[1];
        unsigned int ua[8] = { a0.x, a0.y, a0.z, a0.w, a1.x, a1.y, a1.z, a1.w };
        unsigned int ub[8] = { b0.x, b0.y, b0.z, b0.w, b1.x, b1.y, b1.z, b1.w };
        float dm = 0.0f;
#pragma unroll
        for (int j = 0; j < 8; j++) {
            float alo = __uint_as_float(ua[j] << 16);
            float ahi = __uint_as_float(ua[j] & 0xFFFF0000u);
            float blo = __uint_as_float(ub[j] << 16);
            float bhi = __uint_as_float(ub[j] & 0xFFFF0000u);
            dm += alo * blo + ahi * bhi;
        }
        float d_inter = 1.0f - dm;
        h_inter = fmaxf(DELTA_DIST - d_inter * w[ei], 0.0f);
    }

    // ---- reductions + finalize ----
    float t1 = block_reduce(h_intra, sred);
    if (threadIdx.x == 0) atomicAdd(&g_state.acc[1], t1);
    __syncthreads();
    float t0 = block_reduce(h_inter, sred);
    if (threadIdx.x == 0) atomicAdd(&g_state.acc[0], t0);

    if (threadIdx.x == 0) {
        __threadfence();
        unsigned int v = atomicAdd(&g_state.done, 1u);
        if (v == GRID_F - 1) {
            float inter = atomicAdd(&g_state.acc[0], 0.0f);
            float intra = atomicAdd(&g_state.acc[1], 0.0f);
            out[0] = inter / (float)NEDGE + intra / (float)CSEG;
        }
    }
}

// ---------------------------------------------------------------------------
extern "C" void kernel_launch(void* const* d_in, const int* in_sizes, int n_in,
                              void* d_out, int out_size) {
    const float* emb   = (const float*)d_in[0];   // (1,16,1024,1024) f32
    const float* w     = (const float*)d_in[1];   // (NE,) f32
    const int*   seg   = (const int*)  d_in[2];   // (1,1,1024,1024) i32
    const int*   edges = (const int*)  d_in[3];   // (2,NE) i32
    float*       out   = (float*)d_out;

    static void* state_ptr = nullptr;             // resolved once; fixed addr
    if (!state_ptr) cudaGetSymbolAddress(&state_ptr, g_state);

    cudaFuncSetAttribute(k_fused, cudaFuncAttributeMaxDynamicSharedMemorySize, SMEM_DYN);

    // One memset node zeroes sums/counts/acc/done (all-zero bytes).
    cudaMemsetAsync(state_ptr, 0, sizeof(SState));
    k_segsum<<<PIX / 256, 256>>>(emb, seg);
    k_fused <<<GRID_F, TBLK, SMEM_DYN>>>(emb, seg, edges, w, out);
}

// round 16
// speedup vs baseline: 1.0815x; 1.0151x over previous
#include <cuda_runtime.h>
#include <cuda_fp16.h>
#include <cuda_bf16.h>

// Problem constants (fixed by the reference)
#define CSEG 4096
#define ED   16
#define PIX  (1024*1024)
#define NEDGE 16384
#define DELTA_VAR  0.5f
#define DELTA_DIST 1.5f

#define GRID_F 148
#define TBLK   1024
#define STRIDE (GRID_F * TBLK)
#define NGRP   (PIX / 4)

// dynamic smem: 4096 rows x 8 uint32 (bf16x2 means) + 4096 f32 invn
#define SMEM_MEAN_BYTES (CSEG * 8 * 4)                 // 131072
#define SMEM_DYN        (SMEM_MEAN_BYTES + CSEG * 4)   // 147456

// All replay-mutable scratch in ONE struct: a single memset node zeroes it.
// Sums accumulate in packed fp16x2: halves the LTS atomic word count.
struct SState {
    __half2 sums[CSEG * 8];    // 128 KB: 16 fp16 channels per segment row
    float counts[CSEG];
    float acc[2];              // [0]=inter, [1]=intra
    unsigned int done;         // finalize counter
};
__device__ __align__(128) SState g_state;

// ---------------------------------------------------------------------------
__device__ __forceinline__ float warp_reduce(float v) {
    v += __shfl_down_sync(0xFFFFFFFFu, v, 16);
    v += __shfl_down_sync(0xFFFFFFFFu, v, 8);
    v += __shfl_down_sync(0xFFFFFFFFu, v, 4);
    v += __shfl_down_sync(0xFFFFFFFFu, v, 2);
    v += __shfl_down_sync(0xFFFFFFFFu, v, 1);
    return v;
}

__device__ __forceinline__ float block_reduce(float v, float* s) {
    int lane = threadIdx.x & 31;
    int wid  = threadIdx.x >> 5;
    v = warp_reduce(v);
    if (lane == 0) s[wid] = v;
    __syncthreads();
    if (wid == 0) {
        v = (lane < (TBLK >> 5)) ? s[lane] : 0.0f;
        v = warp_reduce(v);
    }
    return v;
}

// uint4 component select (compile-time under full unroll)
__device__ __forceinline__ unsigned int u4c(const uint4& t, int j) {
    return j == 0 ? t.x : j == 1 ? t.y : j == 2 ? t.z : t.w;
}
// bf16 half-word unpack: e even -> low half, e odd -> high half
__device__ __forceinline__ float bsel(unsigned int m, int e) {
    return (e & 1) ? __uint_as_float(m & 0xFFFF0000u)
                   : __uint_as_float(m << 16);
}

// ---------------------------------------------------------------------------
// k_segsum: segment sums in packed fp16x2 (8 atomic words/pixel vs 16) + count.
__global__ void __launch_bounds__(256) k_segsum(const float* __restrict__ emb,
                                                const int*   __restrict__ seg) {
    int p = blockIdx.x * blockDim.x + threadIdx.x;
    int c = seg[p];
    atomicAdd(&g_state.counts[c], 1.0f);
    float v[ED];
#pragma unroll
    for (int e = 0; e < ED; e++) v[e] = emb[(size_t)e * PIX + p];
    unsigned int h[8];
#pragma unroll
    for (int j = 0; j < 8; j++) {
        __half2 x = __floats2half2_rn(v[2 * j], v[2 * j + 1]);
        h[j] = *(unsigned int*)&x;
    }
    char* base = (char*)&g_state.sums[c * 8];
    asm volatile("red.global.add.noftz.v2.f16x2 [%0], {%1, %2};"
                 :: "l"(base +  0), "r"(h[0]), "r"(h[1]) : "memory");
    asm volatile("red.global.add.noftz.v2.f16x2 [%0], {%1, %2};"
                 :: "l"(base +  8), "r"(h[2]), "r"(h[3]) : "memory");
    asm volatile("red.global.add.noftz.v2.f16x2 [%0], {%1, %2};"
                 :: "l"(base + 16), "r"(h[4]), "r"(h[5]) : "memory");
    asm volatile("red.global.add.noftz.v2.f16x2 [%0], {%1, %2};"
                 :: "l"(base + 24), "r"(h[6]), "r"(h[7]) : "memory");
}

// k_fused: smem bf16 mean table; intra hinge with 4-pixel float4 groups
// (high MLP); inter hinge over edges; last-block finalize.
__global__ void __launch_bounds__(TBLK, 1) k_fused(const float* __restrict__ emb,
                                                   const int*   __restrict__ seg,
                                                   const int*   __restrict__ edges,
                                                   const float* __restrict__ w,
                                                   float* __restrict__ out) {
    extern __shared__ char dyn[];
    unsigned int* s_mean = (unsigned int*)dyn;               // [CSEG*8] bf16x2
    float*        s_invn = (float*)(dyn + SMEM_MEAN_BYTES);  // [CSEG]
    __shared__ float sred[32];

    const int gid = blockIdx.x * TBLK + threadIdx.x;

    // ---- build the table from fp16 sums: bf16x2 means + fp32 invn ----
    for (int s = threadIdx.x; s < CSEG; s += TBLK) {
        const uint4* src = (const uint4*)&g_state.sums[s * 8];   // 32 B row
        uint4 A = src[0], B = src[1];
        unsigned int sw[8] = { A.x, A.y, A.z, A.w, B.x, B.y, B.z, B.w };
        float inv = __frcp_rn(fmaxf(g_state.counts[s], 1.0f));
        unsigned int* row = &s_mean[s * 8];
#pragma unroll
        for (int j = 0; j < 8; j++) {
            float2 f = __half22float2(*(__half2*)&sw[j]);
            __nv_bfloat162 hb = __floats2bfloat162_rn(f.x * inv, f.y * inv);
            row[j] = *(unsigned int*)&hb;
        }
        s_invn[s] = inv;
    }
    __syncthreads();

    // ---- intra term: 4 consecutive pixels per thread, float4 channel loads ----
    float h_intra = 0.0f;
    for (int g = gid; g < NGRP; g += STRIDE) {
        int base = g * 4;
        int4 cs = *(const int4*)(seg + base);
        float d0 = 0.0f, d1 = 0.0f, d2 = 0.0f, d3 = 0.0f;
        {   // channels 0..7 (low uint4 of each table row)
            uint4 t0 = *(const uint4*)&s_mean[cs.x * 8];
            uint4 t1 = *(const uint4*)&s_mean[cs.y * 8];
            uint4 t2 = *(const uint4*)&s_mean[cs.z * 8];
            uint4 t3 = *(const uint4*)&s_mean[cs.w * 8];
#pragma unroll
            for (int e = 0; e < 8; e++) {
                float4 q = *(const float4*)(emb + (size_t)e * PIX + base);
                d0 += bsel(u4c(t0, e >> 1), e) * q.x;
                d1 += bsel(u4c(t1, e >> 1), e) * q.y;
                d2 += bsel(u4c(t2, e >> 1), e) * q.z;
                d3 += bsel(u4c(t3, e >> 1), e) * q.w;
            }
        }
        {   // channels 8..15 (high uint4 of each table row)
            uint4 t0 = *(const uint4*)&s_mean[cs.x * 8 + 4];
            uint4 t1 = *(const uint4*)&s_mean[cs.y * 8 + 4];
            uint4 t2 = *(const uint4*)&s_mean[cs.z * 8 + 4];
            uint4 t3 = *(const uint4*)&s_mean[cs.w * 8 + 4];
#pragma unroll
            for (int e = 0; e < 8; e++) {
                float4 q = *(const float4*)(emb + (size_t)(e + 8) * PIX + base);
                d0 += bsel(u4c(t0, e >> 1), e) * q.x;
                d1 += bsel(u4c(t1, e >> 1), e) * q.y;
                d2 += bsel(u4c(t2, e >> 1), e) * q.z;
                d3 += bsel(u4c(t3, e >> 1), e) * q.w;
            }
        }
        // (1 - dot) - DELTA_VAR = 0.5 - dot, then per-pixel / n
        h_intra += fmaxf(0.5f - d0, 0.0f) * s_invn[cs.x]
                 + fmaxf(0.5f - d1, 0.0f) * s_invn[cs.y]
                 + fmaxf(0.5f - d2, 0.0f) * s_invn[cs.z]
                 + fmaxf(0.5f - d3, 0.0f) * s_invn[cs.w];
    }

    // ---- inter term: first 16 blocks cover all 16384 edges ----
    float h_inter = 0.0f;
    if (gid < NEDGE) {
        int eu = edges[gid];
        int ev = edges[NEDGE + gid];
        const uint4* ru4 = (const uint4*)&s_mean[eu * 8];
        const uint4* rv4 = (const uint4*)&s_mean[ev * 8];
        uint4 a0 = ru4[0], a1 = ru4[1], b0 = rv4[0], b1 = rv4[1];
        unsigned int ua[8] = { a0.x, a0.y, a0.z, a0.w, a1.x, a1.y, a1.z, a1.w };
        unsigned int ub[8] = { b0.x, b0.y, b0.z, b0.w, b1.x, b1.y, b1.z, b1.w };
        float dm = 0.0f;
#pragma unroll
        for (int j = 0; j < 8; j++) {
            float alo = __uint_as_float(ua[j] << 16);
            float ahi = __uint_as_float(ua[j] & 0xFFFF0000u);
            float blo = __uint_as_float(ub[j] << 16);
            float bhi = __uint_as_float(ub[j] & 0xFFFF0000u);
            dm += alo * blo + ahi * bhi;
        }
        float d_inter = 1.0f - dm;
        h_inter = fmaxf(DELTA_DIST - d_inter * w[gid], 0.0f);
    }

    // ---- reductions + finalize ----
    float t1 = block_reduce(h_intra, sred);
    if (threadIdx.x == 0) atomicAdd(&g_state.acc[1], t1);
    __syncthreads();
    float t0 = block_reduce(h_inter, sred);
    if (threadIdx.x == 0) atomicAdd(&g_state.acc[0], t0);

    if (threadIdx.x == 0) {
        __threadfence();
        unsigned int v = atomicAdd(&g_state.done, 1u);
        if (v == GRID_F - 1) {
            float inter = atomicAdd(&g_state.acc[0], 0.0f);
            float intra = atomicAdd(&g_state.acc[1], 0.0f);
            out[0] = inter / (float)NEDGE + intra / (float)CSEG;
        }
    }
}

// ---------------------------------------------------------------------------
extern "C" void kernel_launch(void* const* d_in, const int* in_sizes, int n_in,
                              void* d_out, int out_size) {
    const float* emb   = (const float*)d_in[0];   // (1,16,1024,1024) f32
    const float* w     = (const float*)d_in[1];   // (NE,) f32
    const int*   seg   = (const int*)  d_in[2];   // (1,1,1024,1024) i32
    const int*   edges = (const int*)  d_in[3];   // (2,NE) i32
    float*       out   = (float*)d_out;

    static void* state_ptr = nullptr;             // resolved once; fixed addr
    if (!state_ptr) cudaGetSymbolAddress(&state_ptr, g_state);

    cudaFuncSetAttribute(k_fused, cudaFuncAttributeMaxDynamicSharedMemorySize, SMEM_DYN);

    // One memset node zeroes sums/counts/acc/done (all-zero bytes).
    cudaMemsetAsync(state_ptr, 0, sizeof(SState));
    k_segsum<<<PIX / 256, 256>>>(emb, seg);
    k_fused <<<GRID_F, TBLK, SMEM_DYN>>>(emb, seg, edges, w, out);
}